// round 13
// baseline (speedup 1.0000x reference)
#include <cuda_runtime.h>
#include <cuda_bf16.h>
#include <math.h>
#include <stdint.h>
#include <cstdint>

// ---------------- problem constants ----------------
#define Bc      8
#define Sc      1120
#define Dc      768
#define Hc      12
#define DHc     64
#define NLc     8
#define Vc      128
#define LATENTc 1024
#define TAc     1000
#define Lc      90
#define MROWS   (Bc*Sc)      // 8960
#define MAUD    (Bc*TAc)     // 8000

typedef __nv_bfloat16 bf16;
typedef unsigned int u32;

// ---------------- scratch (device globals; no allocation allowed) ----------------
__device__ float g_x[MROWS*Dc];            // residual stream (fp32, COMPACTED rows)
__device__ bf16  g_hb[MROWS*Dc];           // LN output (bf16, compacted)
__device__ bf16  g_qkvb[MROWS*3*Dc];       // qkv (bf16, compacted)
__device__ bf16  g_attnb[MROWS*Dc];        // attention output (bf16, compacted)
__device__ bf16  g_fcb[MROWS*4*Dc];        // mlp hidden after gelu (bf16, compacted)
__device__ float g_audioH[MAUD*Dc];        // projected audio (fp32, NOT compacted)
__device__ float g_acc[2];                 // loss accumulators
__device__ int   g_need[Bc];               // al[b]+ll[b]
__device__ int   g_need64[Bc];             // ceil(need/64)*64
__device__ int   g_coff[Bc+1];             // prefix of need64; g_coff[Bc] = total rows

// bf16 weight / input copies
__device__ bf16 wb_qkv  [NLc*3*Dc*Dc];
__device__ bf16 wb_attno[NLc*Dc*Dc];
__device__ bf16 wb_fc   [NLc*4*Dc*Dc];
__device__ bf16 wb_mlpo [NLc*4*Dc*Dc];
__device__ bf16 wb_audio[Dc*LATENTc];
__device__ bf16 g_audio_b[Bc*TAc*LATENTc];

// ---------------- small kernels ----------------
__global__ void init_kernel(const int* __restrict__ alen, const int* __restrict__ llen)
{
    if (threadIdx.x == 0) {
        g_acc[0] = 0.f; g_acc[1] = 0.f;
        int off = 0;
        for (int b = 0; b < Bc; b++) {
            int nd = alen[b] + llen[b];
            int nd64 = (nd + 63) & ~63;
            g_need[b] = nd;
            g_need64[b] = nd64;
            g_coff[b] = off;
            off += nd64;
        }
        g_coff[Bc] = off;
    }
}

__global__ void f2b_kernel(const float* __restrict__ s, bf16* __restrict__ d, int n)
{
    int i = (blockIdx.x * blockDim.x + threadIdx.x) * 4;
    if (i >= n) return;
    float4 v = *(const float4*)(s + i);
    __nv_bfloat162* d2 = (__nv_bfloat162*)(d + i);
    d2[0] = __floats2bfloat162_rn(v.x, v.y);
    d2[1] = __floats2bfloat162_rn(v.z, v.w);
}

// ---------------- mma helpers ----------------
__device__ __forceinline__ void ldsm4(u32& r0, u32& r1, u32& r2, u32& r3, u32 addr)
{
    asm volatile("ldmatrix.sync.aligned.m8n8.x4.shared.b16 {%0,%1,%2,%3}, [%4];"
                 : "=r"(r0), "=r"(r1), "=r"(r2), "=r"(r3) : "r"(addr));
}
__device__ __forceinline__ void ldsm4t(u32& r0, u32& r1, u32& r2, u32& r3, u32 addr)
{
    asm volatile("ldmatrix.sync.aligned.m8n8.x4.trans.shared.b16 {%0,%1,%2,%3}, [%4];"
                 : "=r"(r0), "=r"(r1), "=r"(r2), "=r"(r3) : "r"(addr));
}
__device__ __forceinline__ void mma16816(float* c, const u32* a, u32 b0, u32 b1)
{
    asm volatile("mma.sync.aligned.m16n8k16.row.col.f32.bf16.bf16.f32 "
                 "{%0,%1,%2,%3}, {%4,%5,%6,%7}, {%8,%9}, {%0,%1,%2,%3};"
                 : "+f"(c[0]), "+f"(c[1]), "+f"(c[2]), "+f"(c[3])
                 : "r"(a[0]), "r"(a[1]), "r"(a[2]), "r"(a[3]), "r"(b0), "r"(b1));
}
__device__ __forceinline__ void cpasync16(u32 dst, const void* src)
{
    asm volatile("cp.async.cg.shared.global [%0], [%1], 16;" :: "r"(dst), "l"(src));
}
__device__ __forceinline__ u32 packbf(float a, float b)
{
    __nv_bfloat162 h = __floats2bfloat162_rn(a, b);
    return *(u32*)&h;
}
__device__ __forceinline__ float gelu_erf(float v)
{
    return 0.5f * v * (1.f + erff(v * 0.70710678118654752f));
}

// ---------------- bf16 tensor-core GEMM (R9 config: BM=128, BN=64, 3 CTA/SM) ----
// Culling: need==0 -> none. rows_pb>0 -> per-batch (audio path).
// rows_pb==0 -> need points to a single device int (total compacted rows).
#define NST        4
#define A_BY       (128u * 40u * 2u)           // 10240
#define B_BY       (64u * 40u * 2u)            // 5120
#define STG_BY     (A_BY + B_BY)               // 15360
#define GEMM_SMEM  (NST * STG_BY)              // 61440

template<int EPI, int OUTBF>
__global__ __launch_bounds__(256, 3)
void gemm_bf16(const bf16* __restrict__ A, const bf16* __restrict__ W,
               const float* __restrict__ aux, void* __restrict__ Cv,
               int M, int N, int K,
               const int* __restrict__ need, int rows_pb)
{
    extern __shared__ __align__(16) bf16 smdyn[];
    const int tid = threadIdx.x;
    const int warp = tid >> 5, lane = tid & 31;
    const int wm = (warp >> 1) * 32, wn = (warp & 1) * 32;
    const int m0 = blockIdx.y * 128, n0 = blockIdx.x * 64;

    if (need) {
        if (rows_pb == 0) {
            if (m0 >= need[0]) return;       // compacted: uniform limit
        } else {
            bool ok = false;
            int b0 = m0 / rows_pb, b1 = (m0 + 127) / rows_pb;
            if (b1 >= Bc) b1 = Bc - 1;
            for (int b = b0; b <= b1; b++) {
                int sstart = m0 > b * rows_pb ? m0 - b * rows_pb : 0;
                if (sstart < need[b]) { ok = true; break; }
            }
            if (!ok) return;
        }
    }

    float acc[2][4][4];
#pragma unroll
    for (int i = 0; i < 2; i++)
#pragma unroll
        for (int j = 0; j < 4; j++)
#pragma unroll
            for (int k = 0; k < 4; k++) acc[i][j][k] = 0.f;

    const int lr = tid >> 2;
    const int lc = (tid & 3) * 8;
    int ar0 = m0 + lr;      if (ar0 >= M) ar0 = M - 1;
    int ar1 = m0 + 64 + lr; if (ar1 >= M) ar1 = M - 1;
    const bf16* Ap0 = A + (size_t)ar0 * K + lc;
    const bf16* Ap1 = A + (size_t)ar1 * K + lc;
    const bf16* Wp0 = W + (size_t)(n0 + lr) * K + lc;

    const u32 base = (u32)__cvta_generic_to_shared(smdyn);
    const u32 dA0 = (u32)((lr * 40 + lc) * 2);
    const u32 dA1 = (u32)(((lr + 64) * 40 + lc) * 2);

    const int nk = K >> 5;

#pragma unroll
    for (int t = 0; t < NST - 1; t++) {
        if (t < nk) {
            u32 sb = base + (u32)t * STG_BY;
            const int ko = t * 32;
            cpasync16(sb + dA0, Ap0 + ko);
            cpasync16(sb + dA1, Ap1 + ko);
            cpasync16(sb + A_BY + dA0, Wp0 + ko);
        }
        asm volatile("cp.async.commit_group;");
    }

    for (int kb = 0; kb < nk; kb++) {
        const int s = kb & (NST - 1);
        const int rem = nk - kb;
        if (rem >= 3)      asm volatile("cp.async.wait_group 2;");
        else if (rem == 2) asm volatile("cp.async.wait_group 1;");
        else               asm volatile("cp.async.wait_group 0;");
        __syncthreads();

        if (kb + NST - 1 < nk) {
            u32 sb = base + (u32)((kb + NST - 1) & (NST - 1)) * STG_BY;
            const int ko = (kb + NST - 1) * 32;
            cpasync16(sb + dA0, Ap0 + ko);
            cpasync16(sb + dA1, Ap1 + ko);
            cpasync16(sb + A_BY + dA0, Wp0 + ko);
            asm volatile("cp.async.commit_group;");
        }

        const u32 aBase = base + (u32)s * STG_BY;
        const u32 bBase = aBase + A_BY;
#pragma unroll
        for (int ks = 0; ks < 2; ks++) {
            u32 a[2][4];
#pragma unroll
            for (int mf = 0; mf < 2; mf++) {
                u32 addr = aBase +
                    (u32)(((wm + mf * 16 + (lane & 15)) * 40 + ks * 16 + (lane >> 4) * 8) * 2);
                ldsm4(a[mf][0], a[mf][1], a[mf][2], a[mf][3], addr);
            }
            u32 b[2][4];
#pragma unroll
            for (int ng = 0; ng < 2; ng++) {
                u32 addr = bBase +
                    (u32)(((wn + ng * 16 + (lane & 15)) * 40 + ks * 16 + (lane >> 4) * 8) * 2);
                ldsm4(b[ng][0], b[ng][1], b[ng][2], b[ng][3], addr);
            }
#pragma unroll
            for (int mf = 0; mf < 2; mf++)
#pragma unroll
                for (int nf = 0; nf < 4; nf++) {
                    const int ng = nf >> 1, hi = nf & 1;
                    mma16816(acc[mf][nf], a[mf], b[ng][hi], b[ng][2 + hi]);
                }
        }
    }

    const int rw = lane >> 2, cp2 = (lane & 3) * 2;
#pragma unroll
    for (int mf = 0; mf < 2; mf++) {
#pragma unroll
        for (int half = 0; half < 2; half++) {
            const int m = m0 + wm + mf * 16 + half * 8 + rw;
            if (m >= M) continue;
#pragma unroll
            for (int nf = 0; nf < 4; nf++) {
                const int n = n0 + wn + nf * 8 + cp2;
                float v0 = acc[mf][nf][half * 2 + 0];
                float v1 = acc[mf][nf][half * 2 + 1];
                if (EPI == 1) { v0 += aux[n]; v1 += aux[n + 1]; }
                if (EPI == 2) { v0 = gelu_erf(v0); v1 = gelu_erf(v1); }
                if (EPI == 3) {
                    const float* r = aux + (size_t)m * N + n;
                    v0 += r[0]; v1 += r[1];
                }
                if (OUTBF == 0) {
                    *(float2*)((float*)Cv + (size_t)m * N + n) = make_float2(v0, v1);
                } else {
                    *(__nv_bfloat162*)((bf16*)Cv + (size_t)m * N + n) =
                        __floats2bfloat162_rn(v0, v1);
                }
            }
        }
    }
}

// ---------------- sinusoidal position ----------------
__device__ __forceinline__ float sinu_pos(int pos, int d)
{
    const int half = Dc / 2;  // 384
    int i = (d < half) ? d : d - half;
    float invf = expf(-((float)i / (float)half) * 9.210340371976184f); // ln(10000)
    float ang = (float)pos * invf;
    return (d < half) ? sinf(ang) : cosf(ang);
}

// ---------------- embedding assembly (writes COMPACTED rows) ----------------
__global__ void embed_kernel(float* __restrict__ x,
                             const float* __restrict__ audioH,
                             const float* __restrict__ text_emb,
                             const int* __restrict__ labels,
                             const int* __restrict__ alen,
                             const int* __restrict__ llen,
                             const float* __restrict__ start_emb,
                             const float* __restrict__ aps,
                             const float* __restrict__ tps)
{
    int row = blockIdx.x;         // b*S + s (logical)
    int b = row / Sc, s = row % Sc;
    if (s >= g_need64[b]) return;              // beyond padded extent
    int crow = g_coff[b] + s;                  // compacted row
    int al = alen[b], ll = llen[b];
    float apos = *aps, tpos = *tps;
    for (int d = threadIdx.x; d < Dc; d += blockDim.x) {
        float v;
        if (s < al) {
            v = audioH[(size_t)(b * TAc + s) * Dc + d] + sinu_pos(s, d) * apos;
        } else if (s == al) {
            v = start_emb[d];
        } else if (s < al + ll) {
            int j = s - al - 1;
            v = text_emb[(size_t)labels[b * Lc + j] * Dc + d] + sinu_pos(j, d) * tpos;
        } else {
            v = 0.f;                           // padding rows (need..need64)
        }
        x[(size_t)crow * Dc + d] = v;
    }
}

// ---------------- LayerNorm (gamma only, eps 1e-5), bf16 out ----------------
__global__ __launch_bounds__(256)
void ln_kernel(const float* __restrict__ x, const float* __restrict__ g,
               bf16* __restrict__ out, const int* __restrict__ total)
{
    __shared__ float red[16];
    int row = blockIdx.x, t = threadIdx.x;
    if (row >= total[0]) return;               // beyond compacted extent
    const float* xr = x + (size_t)row * Dc;
    float v0 = xr[t], v1 = xr[t + 256], v2 = xr[t + 512];
    float s = v0 + v1 + v2;
    float q = v0 * v0 + v1 * v1 + v2 * v2;
#pragma unroll
    for (int o = 16; o > 0; o >>= 1) {
        s += __shfl_xor_sync(0xffffffffu, s, o);
        q += __shfl_xor_sync(0xffffffffu, q, o);
    }
    int w = t >> 5;
    if ((t & 31) == 0) { red[w] = s; red[w + 8] = q; }
    __syncthreads();
    if (t < 32) {
        float ss = (t < 8) ? red[t] : 0.f;
        float qq = (t < 8) ? red[t + 8] : 0.f;
#pragma unroll
        for (int o = 4; o > 0; o >>= 1) {
            ss += __shfl_xor_sync(0xffffffffu, ss, o);
            qq += __shfl_xor_sync(0xffffffffu, qq, o);
        }
        if (t == 0) {
            float mean = ss * (1.f / 768.f);
            float var = qq * (1.f / 768.f) - mean * mean;
            red[0] = mean;
            red[1] = rsqrtf(var + 1e-5f);
        }
    }
    __syncthreads();
    float mean = red[0], rstd = red[1];
    bf16* orow = out + (size_t)row * Dc;
    orow[t]       = __float2bfloat16((v0 - mean) * rstd * g[t]);
    orow[t + 256] = __float2bfloat16((v1 - mean) * rstd * g[t + 256]);
    orow[t + 512] = __float2bfloat16((v2 - mean) * rstd * g[t + 512]);
}

// ---------------- flash attention (causal, dh=64, bf16 mma.sync, compacted) ----
// block = 128 threads (4 warps); each block: one (b,h), 64 q rows; warp = 16 rows.
// Rows of batch b live at compacted offset g_coff[b]; local indices for masks.
__global__ __launch_bounds__(128)
void attn_kernel(const bf16* __restrict__ qkv, bf16* __restrict__ out)
{
    __shared__ __align__(16) bf16 Qs[64 * 72];
    __shared__ __align__(16) bf16 Ks[64 * 72];
    __shared__ __align__(16) bf16 Vs[64 * 72];

    const int qt = blockIdx.x;              // 0..17
    const int bh = blockIdx.y;              // b*H + h
    const int b = bh / Hc, h = bh % Hc;
    if (qt * 64 >= g_need64[b]) return;     // dead query tile (exact: 64-aligned)
    const int coff = g_coff[b];
    const int tid = threadIdx.x;
    const int warp = tid >> 5, lane = tid & 31;
    const int rstride = 3 * Dc;             // 2304

    const bf16* base = qkv + (size_t)coff * rstride + h * DHc;
    bf16* obase = out + (size_t)coff * Dc + h * DHc;

    // load Q tile [64 rows][64 d] (all rows exist: qt*64+63 < need64)
#pragma unroll
    for (int i = 0; i < 4; i++) {
        int c = i * 128 + tid;
        int row = c >> 3, seg = c & 7;
        int qg = qt * 64 + row;
        *(uint4*)&Qs[row * 72 + seg * 8] =
            *(const uint4*)(base + (size_t)qg * rstride + seg * 8);
    }

    const u32 qb = (u32)__cvta_generic_to_shared(Qs);
    const u32 kb = (u32)__cvta_generic_to_shared(Ks);
    const u32 vbs = (u32)__cvta_generic_to_shared(Vs);

    float oacc[8][4];
#pragma unroll
    for (int i = 0; i < 8; i++)
#pragma unroll
        for (int j = 0; j < 4; j++) oacc[i][j] = 0.f;
    float mrow0 = -1e30f, mrow1 = -1e30f, lrow0 = 0.f, lrow1 = 0.f;

    const int r = lane >> 2;
    const int c2 = (lane & 3) * 2;
    const int m0w = warp * 16;
    const int qg0 = qt * 64 + m0w + r;      // local (within batch)
    const int qg1 = qg0 + 8;
    const u32 lrow_addr = (u32)((m0w + (lane & 15)) * 72 + (lane >> 4) * 8);

    __syncthreads();

    for (int kt = 0; kt <= qt; kt++) {
        // load K,V tiles (rows kt*64..+63 all exist since kt <= qt)
#pragma unroll
        for (int i = 0; i < 4; i++) {
            int c = i * 128 + tid;
            int row = c >> 3, seg = c & 7;
            int kg = kt * 64 + row;
            const bf16* src = base + (size_t)kg * rstride + seg * 8;
            *(uint4*)&Ks[row * 72 + seg * 8] = *(const uint4*)(src + Dc);
            *(uint4*)&Vs[row * 72 + seg * 8] = *(const uint4*)(src + 2 * Dc);
        }
        __syncthreads();

        // S = Q K^T  (m16 x n64 per warp)
        float sacc[8][4];
#pragma unroll
        for (int i = 0; i < 8; i++)
#pragma unroll
            for (int j = 0; j < 4; j++) sacc[i][j] = 0.f;
#pragma unroll
        for (int ks = 0; ks < 4; ks++) {
            u32 aq[4];
            ldsm4(aq[0], aq[1], aq[2], aq[3],
                  qb + (lrow_addr + ks * 16) * 2);
            u32 bk[4][4];
#pragma unroll
            for (int ng = 0; ng < 4; ng++)
                ldsm4(bk[ng][0], bk[ng][1], bk[ng][2], bk[ng][3],
                      kb + (u32)(((ng * 16 + (lane & 15)) * 72 + ks * 16 + (lane >> 4) * 8) * 2));
#pragma unroll
            for (int nf = 0; nf < 8; nf++)
                mma16816(sacc[nf], aq, bk[nf >> 1][nf & 1], bk[nf >> 1][2 + (nf & 1)]);
        }

        // online softmax on fragments (local indices; mask is assignment -> kills NaN)
        float mx0 = -1e30f, mx1 = -1e30f;
#pragma unroll
        for (int nf = 0; nf < 8; nf++) {
#pragma unroll
            for (int e = 0; e < 2; e++) {
                int kg = kt * 64 + nf * 8 + c2 + e;
                float s0 = sacc[nf][e] * 0.125f;
                float s1 = sacc[nf][2 + e] * 0.125f;
                if (kg > qg0) s0 = -1e30f;
                if (kg > qg1) s1 = -1e30f;
                sacc[nf][e] = s0; sacc[nf][2 + e] = s1;
                mx0 = fmaxf(mx0, s0); mx1 = fmaxf(mx1, s1);
            }
        }
        mx0 = fmaxf(mx0, __shfl_xor_sync(0xffffffffu, mx0, 1));
        mx0 = fmaxf(mx0, __shfl_xor_sync(0xffffffffu, mx0, 2));
        mx1 = fmaxf(mx1, __shfl_xor_sync(0xffffffffu, mx1, 1));
        mx1 = fmaxf(mx1, __shfl_xor_sync(0xffffffffu, mx1, 2));
        float mn0 = fmaxf(mrow0, mx0), mn1 = fmaxf(mrow1, mx1);
        float sum0 = 0.f, sum1 = 0.f;
#pragma unroll
        for (int nf = 0; nf < 8; nf++) {
#pragma unroll
            for (int e = 0; e < 2; e++) {
                float p0 = __expf(sacc[nf][e] - mn0);
                float p1 = __expf(sacc[nf][2 + e] - mn1);
                sacc[nf][e] = p0; sacc[nf][2 + e] = p1;
                sum0 += p0; sum1 += p1;
            }
        }
        sum0 += __shfl_xor_sync(0xffffffffu, sum0, 1);
        sum0 += __shfl_xor_sync(0xffffffffu, sum0, 2);
        sum1 += __shfl_xor_sync(0xffffffffu, sum1, 1);
        sum1 += __shfl_xor_sync(0xffffffffu, sum1, 2);
        float corr0 = __expf(mrow0 - mn0), corr1 = __expf(mrow1 - mn1);
        lrow0 = lrow0 * corr0 + sum0;
        lrow1 = lrow1 * corr1 + sum1;
        mrow0 = mn0; mrow1 = mn1;
#pragma unroll
        for (int nd = 0; nd < 8; nd++) {
            oacc[nd][0] *= corr0; oacc[nd][1] *= corr0;
            oacc[nd][2] *= corr1; oacc[nd][3] *= corr1;
        }

        // P fragments (in-register: S C-frag -> PV A-frag)
        u32 ap[4][4];
#pragma unroll
        for (int j = 0; j < 4; j++) {
            ap[j][0] = packbf(sacc[2 * j][0], sacc[2 * j][1]);
            ap[j][1] = packbf(sacc[2 * j][2], sacc[2 * j][3]);
            ap[j][2] = packbf(sacc[2 * j + 1][0], sacc[2 * j + 1][1]);
            ap[j][3] = packbf(sacc[2 * j + 1][2], sacc[2 * j + 1][3]);
        }

        // O += P V   (V via ldmatrix.trans: B[n=d][k])
#pragma unroll
        for (int j = 0; j < 4; j++) {
            u32 vv[4][4];
#pragma unroll
            for (int ng = 0; ng < 4; ng++)
                ldsm4t(vv[ng][0], vv[ng][1], vv[ng][2], vv[ng][3],
                       vbs + (u32)(((j * 16 + (lane & 15)) * 72 + ng * 16 + (lane >> 4) * 8) * 2));
#pragma unroll
            for (int nd = 0; nd < 8; nd++) {
                const int ng = nd >> 1, hi = nd & 1;
                mma16816(oacc[nd], ap[j], vv[ng][hi * 2], vv[ng][hi * 2 + 1]);
            }
        }
        __syncthreads();
    }

    // normalize + store (rows always exist within need64)
    float inv0 = 1.f / lrow0, inv1 = 1.f / lrow1;
#pragma unroll
    for (int nd = 0; nd < 8; nd++) {
        int col = nd * 8 + c2;
        *(__nv_bfloat162*)&obase[(size_t)qg0 * Dc + col] =
            __floats2bfloat162_rn(oacc[nd][0] * inv0, oacc[nd][1] * inv0);
        *(__nv_bfloat162*)&obase[(size_t)qg1 * Dc + col] =
            __floats2bfloat162_rn(oacc[nd][2] * inv1, oacc[nd][3] * inv1);
    }
}

// ---------------- loss (gathers from compacted rows) ----------------
__global__ __launch_bounds__(128)
void loss_kernel(const bf16* __restrict__ xf, const float* __restrict__ Wh,
                 const int* __restrict__ labels, const int* __restrict__ alen,
                 const int* __restrict__ llen)
{
    int blk = blockIdx.x;
    int b = blk / Lc, j = blk % Lc;
    if (j >= llen[b]) return;
    int crow = g_coff[b] + alen[b] + j;        // al+j < need <= need64
    __shared__ __align__(16) float lat[768];
    __shared__ float logits[128];
    int t = threadIdx.x;
    const bf16* xr = xf + (size_t)crow * Dc;
    for (int d = t; d < Dc; d += 128) lat[d] = __bfloat162float(xr[d]);
    __syncthreads();
    const float4* w4 = (const float4*)(Wh) + (size_t)t * 192;
    const float4* l4 = (const float4*)lat;
    float acc = 0.f;
#pragma unroll 4
    for (int d = 0; d < 192; d++) {
        float4 a = l4[d], bb = w4[d];
        acc += a.x * bb.x + a.y * bb.y + a.z * bb.z + a.w * bb.w;
    }
    logits[t] = acc;
    __syncthreads();
    if (t == 0) {
        float mx = -1e30f;
        for (int i = 0; i < Vc; i++) mx = fmaxf(mx, logits[i]);
        float se = 0.f;
        for (int i = 0; i < Vc; i++) se += __expf(logits[i] - mx);
        int lab = labels[b * Lc + j];
        float nll = -(logits[lab] - mx - logf(se));
        atomicAdd(&g_acc[0], nll);
        atomicAdd(&g_acc[1], 1.0f);
    }
}

__global__ void finalize_kernel(float* out) { out[0] = g_acc[0] / g_acc[1]; }

// ---------------- host launch ----------------
extern "C" void kernel_launch(void* const* d_in, const int* in_sizes, int n_in,
                              void* d_out, int out_size)
{
    const float* audio = 0;
    const int* labels = 0;
    const int* alen = 0;
    const int* llen = 0;
    for (int i = 0; i < 4; i++) {
        int sz = in_sizes[i];
        if (sz == Bc * TAc * LATENTc) { audio = (const float*)d_in[i]; }
        else if (sz == Bc * Lc) { labels = (const int*)d_in[i]; }
        else if (sz == Bc) {
            if (alen == 0) { alen = (const int*)d_in[i]; }
            else { llen = (const int*)d_in[i]; }
        }
    }
    const float* text_emb_w   = (const float*)d_in[4];
    const float* text_head_w  = (const float*)d_in[5];
    const float* audio_proj_w = (const float*)d_in[6];
    const float* audio_proj_b = (const float*)d_in[7];
    const float* start_emb    = (const float*)d_in[8];
    const float* aps          = (const float*)d_in[9];
    const float* tps          = (const float*)d_in[10];
    const float* ln1_g        = (const float*)d_in[11];
    const float* ln2_g        = (const float*)d_in[12];
    const float* lnf_g        = (const float*)d_in[13];
    const float* qkv_w        = (const float*)d_in[14];
    const float* attn_o_w     = (const float*)d_in[15];
    const float* fc_w         = (const float*)d_in[16];
    const float* mlp_o_w      = (const float*)d_in[17];

    void *vpx, *vphb, *vpqkv, *vpattnb, *vpfcb, *vpaudioH, *vcoff;
    void *vwqkv, *vwattno, *vwfc, *vwmlpo, *vwaudio, *vaudiob;
    cudaGetSymbolAddress(&vpx,      g_x);
    cudaGetSymbolAddress(&vphb,     g_hb);
    cudaGetSymbolAddress(&vpqkv,    g_qkvb);
    cudaGetSymbolAddress(&vpattnb,  g_attnb);
    cudaGetSymbolAddress(&vpfcb,    g_fcb);
    cudaGetSymbolAddress(&vpaudioH, g_audioH);
    cudaGetSymbolAddress(&vcoff,    g_coff);
    cudaGetSymbolAddress(&vwqkv,    wb_qkv);
    cudaGetSymbolAddress(&vwattno,  wb_attno);
    cudaGetSymbolAddress(&vwfc,     wb_fc);
    cudaGetSymbolAddress(&vwmlpo,   wb_mlpo);
    cudaGetSymbolAddress(&vwaudio,  wb_audio);
    cudaGetSymbolAddress(&vaudiob,  g_audio_b);

    float* px      = (float*)vpx;
    bf16*  phb     = (bf16*)vphb;
    bf16*  pqkv    = (bf16*)vpqkv;
    bf16*  pattnb  = (bf16*)vpattnb;
    bf16*  pfcb    = (bf16*)vpfcb;
    float* paudioH = (float*)vpaudioH;
    int*   ptotal  = (int*)vcoff + Bc;         // &g_coff[Bc] = total compacted rows
    bf16*  pwqkv   = (bf16*)vwqkv;
    bf16*  pwattno = (bf16*)vwattno;
    bf16*  pwfc    = (bf16*)vwfc;
    bf16*  pwmlpo  = (bf16*)vwmlpo;
    bf16*  pwaudio = (bf16*)vwaudio;
    bf16*  paudiob = (bf16*)vaudiob;

    // opt-in to 60KB dynamic smem for all GEMM instantiations
    cudaFuncSetAttribute(gemm_bf16<0,1>, cudaFuncAttributeMaxDynamicSharedMemorySize, GEMM_SMEM);
    cudaFuncSetAttribute(gemm_bf16<1,0>, cudaFuncAttributeMaxDynamicSharedMemorySize, GEMM_SMEM);
    cudaFuncSetAttribute(gemm_bf16<2,1>, cudaFuncAttributeMaxDynamicSharedMemorySize, GEMM_SMEM);
    cudaFuncSetAttribute(gemm_bf16<3,0>, cudaFuncAttributeMaxDynamicSharedMemorySize, GEMM_SMEM);

    init_kernel<<<1, 32>>>(alen, llen);

    // f32 -> bf16 conversions (weights + audio input)
    {
        int n;
        n = Bc * TAc * LATENTc; f2b_kernel<<<(n / 4 + 255) / 256, 256>>>(audio, paudiob, n);
        n = Dc * LATENTc;       f2b_kernel<<<(n / 4 + 255) / 256, 256>>>(audio_proj_w, pwaudio, n);
        n = NLc * 3 * Dc * Dc;  f2b_kernel<<<(n / 4 + 255) / 256, 256>>>(qkv_w, pwqkv, n);
        n = NLc * Dc * Dc;      f2b_kernel<<<(n / 4 + 255) / 256, 256>>>(attn_o_w, pwattno, n);
        n = NLc * 4 * Dc * Dc;  f2b_kernel<<<(n / 4 + 255) / 256, 256>>>(fc_w, pwfc, n);
        n = NLc * 4 * Dc * Dc;  f2b_kernel<<<(n / 4 + 255) / 256, 256>>>(mlp_o_w, pwmlpo, n);
    }

    // audio projection: not compacted; cull by alen per batch (1000 rows/batch)
    gemm_bf16<1, 0><<<dim3(Dc / 64, (MAUD + 127) / 128), 256, GEMM_SMEM>>>(
        paudiob, pwaudio, audio_proj_b, paudioH, MAUD, Dc, LATENTc, alen, TAc);

    embed_kernel<<<MROWS, 256>>>(px, paudioH, text_emb_w, labels, alen, llen,
                                 start_emb, aps, tps);

    for (int l = 0; l < NLc; l++) {
        ln_kernel<<<MROWS, 256>>>(px, ln1_g + l * Dc, phb, ptotal);
        gemm_bf16<0, 1><<<dim3(3 * Dc / 64, MROWS / 128), 256, GEMM_SMEM>>>(
            phb, pwqkv + (size_t)l * 3 * Dc * Dc, 0, pqkv, MROWS, 3 * Dc, Dc, ptotal, 0);
        attn_kernel<<<dim3((Sc + 63) / 64, Bc * Hc), 128>>>(pqkv, pattnb);
        gemm_bf16<3, 0><<<dim3(Dc / 64, MROWS / 128), 256, GEMM_SMEM>>>(
            pattnb, pwattno + (size_t)l * Dc * Dc, px, px, MROWS, Dc, Dc, ptotal, 0);
        ln_kernel<<<MROWS, 256>>>(px, ln2_g + l * Dc, phb, ptotal);
        gemm_bf16<2, 1><<<dim3(4 * Dc / 64, MROWS / 128), 256, GEMM_SMEM>>>(
            phb, pwfc + (size_t)l * 4 * Dc * Dc, 0, pfcb, MROWS, 4 * Dc, Dc, ptotal, 0);
        gemm_bf16<3, 0><<<dim3(Dc / 64, MROWS / 128), 256, GEMM_SMEM>>>(
            pfcb, pwmlpo + (size_t)l * 4 * Dc * Dc, px, px, MROWS, Dc, 4 * Dc, ptotal, 0);
    }

    ln_kernel<<<MROWS, 256>>>(px, lnf_g, phb, ptotal);
    loss_kernel<<<Bc * Lc, 128>>>(phb, text_head_w, labels, alen, llen);
    finalize_kernel<<<1, 1>>>((float*)d_out);
}

// round 14
// speedup vs baseline: 1.4808x; 1.4808x over previous
#include <cuda_runtime.h>
#include <cuda_bf16.h>
#include <math.h>
#include <stdint.h>
#include <cstdint>

// ---------------- problem constants ----------------
#define Bc      8
#define Sc      1120
#define Dc      768
#define Hc      12
#define DHc     64
#define NLc     8
#define Vc      128
#define LATENTc 1024
#define TAc     1000
#define Lc      90
#define MROWS   (Bc*Sc)      // 8960
#define MAUD    (Bc*TAc)     // 8000

typedef __nv_bfloat16 bf16;
typedef unsigned int u32;

// ---------------- scratch (device globals; no allocation allowed) ----------------
__device__ float g_x[MROWS*Dc];            // residual stream (fp32)
__device__ bf16  g_hb[MROWS*Dc];           // LN output (bf16)
__device__ bf16  g_qkvb[MROWS*3*Dc];       // qkv (bf16, read by attention)
__device__ bf16  g_attnb[MROWS*Dc];        // attention output (bf16)
__device__ bf16  g_fcb[MROWS*4*Dc];        // mlp hidden after gelu (bf16)
__device__ float g_audioH[MAUD*Dc];        // projected audio (fp32)
__device__ float g_acc[2];                 // loss accumulators
__device__ int   g_need[Bc];               // al[b]+ll[b]: rows needed per batch

// bf16 weight / input copies
__device__ bf16 wb_qkv  [NLc*3*Dc*Dc];
__device__ bf16 wb_attno[NLc*Dc*Dc];
__device__ bf16 wb_fc   [NLc*4*Dc*Dc];
__device__ bf16 wb_mlpo [NLc*4*Dc*Dc];
__device__ bf16 wb_audio[Dc*LATENTc];
__device__ bf16 g_audio_b[Bc*TAc*LATENTc];

// ---------------- small kernels ----------------
__global__ void init_kernel(const int* __restrict__ alen, const int* __restrict__ llen)
{
    g_acc[0] = 0.f; g_acc[1] = 0.f;
    if (threadIdx.x < Bc) g_need[threadIdx.x] = alen[threadIdx.x] + llen[threadIdx.x];
}

__global__ void f2b_kernel(const float* __restrict__ s, bf16* __restrict__ d, int n)
{
    int i = (blockIdx.x * blockDim.x + threadIdx.x) * 4;
    if (i >= n) return;
    float4 v = *(const float4*)(s + i);
    __nv_bfloat162* d2 = (__nv_bfloat162*)(d + i);
    d2[0] = __floats2bfloat162_rn(v.x, v.y);
    d2[1] = __floats2bfloat162_rn(v.z, v.w);
}

// ---------------- mma helpers ----------------
__device__ __forceinline__ void ldsm4(u32& r0, u32& r1, u32& r2, u32& r3, u32 addr)
{
    asm volatile("ldmatrix.sync.aligned.m8n8.x4.shared.b16 {%0,%1,%2,%3}, [%4];"
                 : "=r"(r0), "=r"(r1), "=r"(r2), "=r"(r3) : "r"(addr));
}
__device__ __forceinline__ void ldsm4t(u32& r0, u32& r1, u32& r2, u32& r3, u32 addr)
{
    asm volatile("ldmatrix.sync.aligned.m8n8.x4.trans.shared.b16 {%0,%1,%2,%3}, [%4];"
                 : "=r"(r0), "=r"(r1), "=r"(r2), "=r"(r3) : "r"(addr));
}
__device__ __forceinline__ void mma16816(float* c, const u32* a, u32 b0, u32 b1)
{
    asm volatile("mma.sync.aligned.m16n8k16.row.col.f32.bf16.bf16.f32 "
                 "{%0,%1,%2,%3}, {%4,%5,%6,%7}, {%8,%9}, {%0,%1,%2,%3};"
                 : "+f"(c[0]), "+f"(c[1]), "+f"(c[2]), "+f"(c[3])
                 : "r"(a[0]), "r"(a[1]), "r"(a[2]), "r"(a[3]), "r"(b0), "r"(b1));
}
__device__ __forceinline__ void cpasync16(u32 dst, const void* src)
{
    asm volatile("cp.async.cg.shared.global [%0], [%1], 16;" :: "r"(dst), "l"(src));
}
__device__ __forceinline__ u32 packbf(float a, float b)
{
    __nv_bfloat162 h = __floats2bfloat162_rn(a, b);
    return *(u32*)&h;
}
__device__ __forceinline__ float gelu_erf(float v)
{
    return 0.5f * v * (1.f + erff(v * 0.70710678118654752f));
}

// ---------------- bf16 tensor-core GEMM (BM=128, BN=64, 3 CTA/SM) ----------------
#define NST        4
#define A_BY       (128u * 40u * 2u)           // 10240
#define B_BY       (64u * 40u * 2u)            // 5120
#define STG_BY     (A_BY + B_BY)               // 15360
#define GEMM_SMEM  (NST * STG_BY)              // 61440

template<int EPI, int OUTBF>
__global__ __launch_bounds__(256, 3)
void gemm_bf16(const bf16* __restrict__ A, const bf16* __restrict__ W,
               const float* __restrict__ aux, void* __restrict__ Cv,
               int M, int N, int K,
               const int* __restrict__ need, int rows_pb)
{
    extern __shared__ __align__(16) bf16 smdyn[];
    const int tid = threadIdx.x;
    const int warp = tid >> 5, lane = tid & 31;
    const int wm = (warp >> 1) * 32, wn = (warp & 1) * 32;
    const int m0 = blockIdx.y * 128, n0 = blockIdx.x * 64;

    if (need) {   // tile dead-row culling (uniform across block)
        bool ok = false;
        int b0 = m0 / rows_pb, b1 = (m0 + 127) / rows_pb;
        if (b1 >= Bc) b1 = Bc - 1;
        for (int b = b0; b <= b1; b++) {
            int sstart = m0 > b * rows_pb ? m0 - b * rows_pb : 0;
            if (sstart < need[b]) { ok = true; break; }
        }
        if (!ok) return;
    }

    float acc[2][4][4];
#pragma unroll
    for (int i = 0; i < 2; i++)
#pragma unroll
        for (int j = 0; j < 4; j++)
#pragma unroll
            for (int k = 0; k < 4; k++) acc[i][j][k] = 0.f;

    const int lr = tid >> 2;
    const int lc = (tid & 3) * 8;
    int ar0 = m0 + lr;      if (ar0 >= M) ar0 = M - 1;
    int ar1 = m0 + 64 + lr; if (ar1 >= M) ar1 = M - 1;
    const bf16* Ap0 = A + (size_t)ar0 * K + lc;
    const bf16* Ap1 = A + (size_t)ar1 * K + lc;
    const bf16* Wp0 = W + (size_t)(n0 + lr) * K + lc;

    const u32 base = (u32)__cvta_generic_to_shared(smdyn);
    const u32 dA0 = (u32)((lr * 40 + lc) * 2);
    const u32 dA1 = (u32)(((lr + 64) * 40 + lc) * 2);

    const int nk = K >> 5;

#pragma unroll
    for (int t = 0; t < NST - 1; t++) {
        if (t < nk) {
            u32 sb = base + (u32)t * STG_BY;
            const int ko = t * 32;
            cpasync16(sb + dA0, Ap0 + ko);
            cpasync16(sb + dA1, Ap1 + ko);
            cpasync16(sb + A_BY + dA0, Wp0 + ko);
        }
        asm volatile("cp.async.commit_group;");
    }

    for (int kb = 0; kb < nk; kb++) {
        const int s = kb & (NST - 1);
        const int rem = nk - kb;
        if (rem >= 3)      asm volatile("cp.async.wait_group 2;");
        else if (rem == 2) asm volatile("cp.async.wait_group 1;");
        else               asm volatile("cp.async.wait_group 0;");
        __syncthreads();

        if (kb + NST - 1 < nk) {
            u32 sb = base + (u32)((kb + NST - 1) & (NST - 1)) * STG_BY;
            const int ko = (kb + NST - 1) * 32;
            cpasync16(sb + dA0, Ap0 + ko);
            cpasync16(sb + dA1, Ap1 + ko);
            cpasync16(sb + A_BY + dA0, Wp0 + ko);
            asm volatile("cp.async.commit_group;");
        }

        const u32 aBase = base + (u32)s * STG_BY;
        const u32 bBase = aBase + A_BY;
#pragma unroll
        for (int ks = 0; ks < 2; ks++) {
            u32 a[2][4];
#pragma unroll
            for (int mf = 0; mf < 2; mf++) {
                u32 addr = aBase +
                    (u32)(((wm + mf * 16 + (lane & 15)) * 40 + ks * 16 + (lane >> 4) * 8) * 2);
                ldsm4(a[mf][0], a[mf][1], a[mf][2], a[mf][3], addr);
            }
            u32 b[2][4];
#pragma unroll
            for (int ng = 0; ng < 2; ng++) {
                u32 addr = bBase +
                    (u32)(((wn + ng * 16 + (lane & 15)) * 40 + ks * 16 + (lane >> 4) * 8) * 2);
                ldsm4(b[ng][0], b[ng][1], b[ng][2], b[ng][3], addr);
            }
#pragma unroll
            for (int mf = 0; mf < 2; mf++)
#pragma unroll
                for (int nf = 0; nf < 4; nf++) {
                    const int ng = nf >> 1, hi = nf & 1;
                    mma16816(acc[mf][nf], a[mf], b[ng][hi], b[ng][2 + hi]);
                }
        }
    }

    const int rw = lane >> 2, cp2 = (lane & 3) * 2;
#pragma unroll
    for (int mf = 0; mf < 2; mf++) {
#pragma unroll
        for (int half = 0; half < 2; half++) {
            const int m = m0 + wm + mf * 16 + half * 8 + rw;
            if (m >= M) continue;
#pragma unroll
            for (int nf = 0; nf < 4; nf++) {
                const int n = n0 + wn + nf * 8 + cp2;
                float v0 = acc[mf][nf][half * 2 + 0];
                float v1 = acc[mf][nf][half * 2 + 1];
                if (EPI == 1) { v0 += aux[n]; v1 += aux[n + 1]; }
                if (EPI == 2) { v0 = gelu_erf(v0); v1 = gelu_erf(v1); }
                if (EPI == 3) {
                    const float* r = aux + (size_t)m * N + n;
                    v0 += r[0]; v1 += r[1];
                }
                if (OUTBF == 0) {
                    *(float2*)((float*)Cv + (size_t)m * N + n) = make_float2(v0, v1);
                } else {
                    *(__nv_bfloat162*)((bf16*)Cv + (size_t)m * N + n) =
                        __floats2bfloat162_rn(v0, v1);
                }
            }
        }
    }
}

// ---------------- sinusoidal position ----------------
__device__ __forceinline__ float sinu_pos(int pos, int d)
{
    const int half = Dc / 2;  // 384
    int i = (d < half) ? d : d - half;
    float invf = expf(-((float)i / (float)half) * 9.210340371976184f); // ln(10000)
    float ang = (float)pos * invf;
    return (d < half) ? sinf(ang) : cosf(ang);
}

// ---------------- embedding assembly ----------------
__global__ void embed_kernel(float* __restrict__ x,
                             const float* __restrict__ audioH,
                             const float* __restrict__ text_emb,
                             const int* __restrict__ labels,
                             const int* __restrict__ alen,
                             const int* __restrict__ llen,
                             const float* __restrict__ start_emb,
                             const float* __restrict__ aps,
                             const float* __restrict__ tps)
{
    int row = blockIdx.x;         // b*S + s
    int b = row / Sc, s = row % Sc;
    int al = alen[b], ll = llen[b];
    float apos = *aps, tpos = *tps;
    for (int d = threadIdx.x; d < Dc; d += blockDim.x) {
        float v;
        if (s < al) {
            v = audioH[(size_t)(b * TAc + s) * Dc + d] + sinu_pos(s, d) * apos;
        } else if (s == al) {
            v = start_emb[d];
        } else if (s < al + ll) {
            int j = s - al - 1;
            v = text_emb[(size_t)labels[b * Lc + j] * Dc + d] + sinu_pos(j, d) * tpos;
        } else {
            v = 0.f;
        }
        x[(size_t)row * Dc + d] = v;
    }
}

// ---------------- LayerNorm (gamma only, eps 1e-5), bf16 out ----------------
__global__ __launch_bounds__(256)
void ln_kernel(const float* __restrict__ x, const float* __restrict__ g,
               bf16* __restrict__ out, const int* __restrict__ need)
{
    __shared__ float red[16];
    int row = blockIdx.x, t = threadIdx.x;
    if (need && (row % Sc) >= need[row / Sc]) return;   // dead row
    const float* xr = x + (size_t)row * Dc;
    float v0 = xr[t], v1 = xr[t + 256], v2 = xr[t + 512];
    float s = v0 + v1 + v2;
    float q = v0 * v0 + v1 * v1 + v2 * v2;
#pragma unroll
    for (int o = 16; o > 0; o >>= 1) {
        s += __shfl_xor_sync(0xffffffffu, s, o);
        q += __shfl_xor_sync(0xffffffffu, q, o);
    }
    int w = t >> 5;
    if ((t & 31) == 0) { red[w] = s; red[w + 8] = q; }
    __syncthreads();
    if (t < 32) {
        float ss = (t < 8) ? red[t] : 0.f;
        float qq = (t < 8) ? red[t + 8] : 0.f;
#pragma unroll
        for (int o = 4; o > 0; o >>= 1) {
            ss += __shfl_xor_sync(0xffffffffu, ss, o);
            qq += __shfl_xor_sync(0xffffffffu, qq, o);
        }
        if (t == 0) {
            float mean = ss * (1.f / 768.f);
            float var = qq * (1.f / 768.f) - mean * mean;
            red[0] = mean;
            red[1] = rsqrtf(var + 1e-5f);
        }
    }
    __syncthreads();
    float mean = red[0], rstd = red[1];
    bf16* orow = out + (size_t)row * Dc;
    orow[t]       = __float2bfloat16((v0 - mean) * rstd * g[t]);
    orow[t + 256] = __float2bfloat16((v1 - mean) * rstd * g[t + 256]);
    orow[t + 512] = __float2bfloat16((v2 - mean) * rstd * g[t + 512]);
}

// ---------------- flash attention (causal, dh=64, bf16 mma.sync) --------------
// block = 128 threads (4 warps); each block: one (b,h), 64 q rows; warp = 16 rows.
__global__ __launch_bounds__(128)
void attn_kernel(const bf16* __restrict__ qkv, bf16* __restrict__ out,
                 const int* __restrict__ need)
{
    __shared__ __align__(16) bf16 Qs[64 * 72];
    __shared__ __align__(16) bf16 Ks[64 * 72];
    __shared__ __align__(16) bf16 Vs[64 * 72];

    const int qt = blockIdx.x;              // 0..17
    const int bh = blockIdx.y;              // b*H + h
    const int b = bh / Hc, h = bh % Hc;
    if (qt * 64 >= need[b]) return;         // dead query tile
    const int tid = threadIdx.x;
    const int warp = tid >> 5, lane = tid & 31;
    const int rstride = 3 * Dc;             // 2304

    const bf16* base = qkv + (size_t)b * Sc * rstride + h * DHc;

    // load Q tile [64 rows][64 d]
#pragma unroll
    for (int i = 0; i < 4; i++) {
        int c = i * 128 + tid;
        int row = c >> 3, seg = c & 7;
        int qg = qt * 64 + row; if (qg >= Sc) qg = Sc - 1;
        *(uint4*)&Qs[row * 72 + seg * 8] =
            *(const uint4*)(base + (size_t)qg * rstride + seg * 8);
    }

    const u32 qb = (u32)__cvta_generic_to_shared(Qs);
    const u32 kb = (u32)__cvta_generic_to_shared(Ks);
    const u32 vbs = (u32)__cvta_generic_to_shared(Vs);

    float oacc[8][4];
#pragma unroll
    for (int i = 0; i < 8; i++)
#pragma unroll
        for (int j = 0; j < 4; j++) oacc[i][j] = 0.f;
    float mrow0 = -1e30f, mrow1 = -1e30f, lrow0 = 0.f, lrow1 = 0.f;

    const int r = lane >> 2;
    const int c2 = (lane & 3) * 2;
    const int m0w = warp * 16;
    const int qg0 = qt * 64 + m0w + r;
    const int qg1 = qg0 + 8;
    const u32 lrow_addr = (u32)((m0w + (lane & 15)) * 72 + (lane >> 4) * 8);

    __syncthreads();

    for (int kt = 0; kt <= qt; kt++) {
        // load K,V tiles
#pragma unroll
        for (int i = 0; i < 4; i++) {
            int c = i * 128 + tid;
            int row = c >> 3, seg = c & 7;
            int kg = kt * 64 + row; if (kg >= Sc) kg = Sc - 1;
            const bf16* src = base + (size_t)kg * rstride + seg * 8;
            *(uint4*)&Ks[row * 72 + seg * 8] = *(const uint4*)(src + Dc);
            *(uint4*)&Vs[row * 72 + seg * 8] = *(const uint4*)(src + 2 * Dc);
        }
        __syncthreads();

        // S = Q K^T  (m16 x n64 per warp)
        float sacc[8][4];
#pragma unroll
        for (int i = 0; i < 8; i++)
#pragma unroll
            for (int j = 0; j < 4; j++) sacc[i][j] = 0.f;
#pragma unroll
        for (int ks = 0; ks < 4; ks++) {
            u32 aq[4];
            ldsm4(aq[0], aq[1], aq[2], aq[3],
                  qb + (lrow_addr + ks * 16) * 2);
            u32 bk[4][4];
#pragma unroll
            for (int ng = 0; ng < 4; ng++)
                ldsm4(bk[ng][0], bk[ng][1], bk[ng][2], bk[ng][3],
                      kb + (u32)(((ng * 16 + (lane & 15)) * 72 + ks * 16 + (lane >> 4) * 8) * 2));
#pragma unroll
            for (int nf = 0; nf < 8; nf++)
                mma16816(sacc[nf], aq, bk[nf >> 1][nf & 1], bk[nf >> 1][2 + (nf & 1)]);
        }

        // online softmax on fragments
        float mx0 = -1e30f, mx1 = -1e30f;
#pragma unroll
        for (int nf = 0; nf < 8; nf++) {
#pragma unroll
            for (int e = 0; e < 2; e++) {
                int kg = kt * 64 + nf * 8 + c2 + e;
                float s0 = sacc[nf][e] * 0.125f;
                float s1 = sacc[nf][2 + e] * 0.125f;
                if (kg > qg0) s0 = -1e30f;
                if (kg > qg1) s1 = -1e30f;
                sacc[nf][e] = s0; sacc[nf][2 + e] = s1;
                mx0 = fmaxf(mx0, s0); mx1 = fmaxf(mx1, s1);
            }
        }
        mx0 = fmaxf(mx0, __shfl_xor_sync(0xffffffffu, mx0, 1));
        mx0 = fmaxf(mx0, __shfl_xor_sync(0xffffffffu, mx0, 2));
        mx1 = fmaxf(mx1, __shfl_xor_sync(0xffffffffu, mx1, 1));
        mx1 = fmaxf(mx1, __shfl_xor_sync(0xffffffffu, mx1, 2));
        float mn0 = fmaxf(mrow0, mx0), mn1 = fmaxf(mrow1, mx1);
        float sum0 = 0.f, sum1 = 0.f;
#pragma unroll
        for (int nf = 0; nf < 8; nf++) {
#pragma unroll
            for (int e = 0; e < 2; e++) {
                float p0 = __expf(sacc[nf][e] - mn0);
                float p1 = __expf(sacc[nf][2 + e] - mn1);
                sacc[nf][e] = p0; sacc[nf][2 + e] = p1;
                sum0 += p0; sum1 += p1;
            }
        }
        sum0 += __shfl_xor_sync(0xffffffffu, sum0, 1);
        sum0 += __shfl_xor_sync(0xffffffffu, sum0, 2);
        sum1 += __shfl_xor_sync(0xffffffffu, sum1, 1);
        sum1 += __shfl_xor_sync(0xffffffffu, sum1, 2);
        float corr0 = __expf(mrow0 - mn0), corr1 = __expf(mrow1 - mn1);
        lrow0 = lrow0 * corr0 + sum0;
        lrow1 = lrow1 * corr1 + sum1;
        mrow0 = mn0; mrow1 = mn1;
#pragma unroll
        for (int nd = 0; nd < 8; nd++) {
            oacc[nd][0] *= corr0; oacc[nd][1] *= corr0;
            oacc[nd][2] *= corr1; oacc[nd][3] *= corr1;
        }

        // P fragments (in-register: S C-frag -> PV A-frag)
        u32 ap[4][4];
#pragma unroll
        for (int j = 0; j < 4; j++) {
            ap[j][0] = packbf(sacc[2 * j][0], sacc[2 * j][1]);
            ap[j][1] = packbf(sacc[2 * j][2], sacc[2 * j][3]);
            ap[j][2] = packbf(sacc[2 * j + 1][0], sacc[2 * j + 1][1]);
            ap[j][3] = packbf(sacc[2 * j + 1][2], sacc[2 * j + 1][3]);
        }

        // O += P V   (V via ldmatrix.trans: B[n=d][k])
#pragma unroll
        for (int j = 0; j < 4; j++) {
            u32 vv[4][4];
#pragma unroll
            for (int ng = 0; ng < 4; ng++)
                ldsm4t(vv[ng][0], vv[ng][1], vv[ng][2], vv[ng][3],
                       vbs + (u32)(((j * 16 + (lane & 15)) * 72 + ng * 16 + (lane >> 4) * 8) * 2));
#pragma unroll
            for (int nd = 0; nd < 8; nd++) {
                const int ng = nd >> 1, hi = nd & 1;
                mma16816(oacc[nd], ap[j], vv[ng][hi * 2], vv[ng][hi * 2 + 1]);
            }
        }
        __syncthreads();
    }

    // normalize + store
    float inv0 = 1.f / lrow0, inv1 = 1.f / lrow1;
#pragma unroll
    for (int nd = 0; nd < 8; nd++) {
        int col = h * DHc + nd * 8 + c2;
        if (qg0 < Sc)
            *(__nv_bfloat162*)&out[(size_t)(b * Sc + qg0) * Dc + col] =
                __floats2bfloat162_rn(oacc[nd][0] * inv0, oacc[nd][1] * inv0);
        if (qg1 < Sc)
            *(__nv_bfloat162*)&out[(size_t)(b * Sc + qg1) * Dc + col] =
                __floats2bfloat162_rn(oacc[nd][2] * inv1, oacc[nd][3] * inv1);
    }
}

// ---------------- loss ----------------
__global__ __launch_bounds__(128)
void loss_kernel(const bf16* __restrict__ xf, const float* __restrict__ Wh,
                 const int* __restrict__ labels, const int* __restrict__ alen,
                 const int* __restrict__ llen)
{
    int blk = blockIdx.x;
    int b = blk / Lc, j = blk % Lc;
    if (j >= llen[b]) return;
    int gi = alen[b] + j; if (gi > Sc - 1) gi = Sc - 1;
    __shared__ __align__(16) float lat[768];
    __shared__ float logits[128];
    int t = threadIdx.x;
    const bf16* xr = xf + (size_t)(b * Sc + gi) * Dc;
    for (int d = t; d < Dc; d += 128) lat[d] = __bfloat162float(xr[d]);
    __syncthreads();
    const float4* w4 = (const float4*)(Wh) + (size_t)t * 192;
    const float4* l4 = (const float4*)lat;
    float acc = 0.f;
#pragma unroll 4
    for (int d = 0; d < 192; d++) {
        float4 a = l4[d], bb = w4[d];
        acc += a.x * bb.x + a.y * bb.y + a.z * bb.z + a.w * bb.w;
    }
    logits[t] = acc;
    __syncthreads();
    if (t == 0) {
        float mx = -1e30f;
        for (int i = 0; i < Vc; i++) mx = fmaxf(mx, logits[i]);
        float se = 0.f;
        for (int i = 0; i < Vc; i++) se += __expf(logits[i] - mx);
        int lab = labels[b * Lc + j];
        float nll = -(logits[lab] - mx - logf(se));
        atomicAdd(&g_acc[0], nll);
        atomicAdd(&g_acc[1], 1.0f);
    }
}

__global__ void finalize_kernel(float* out) { out[0] = g_acc[0] / g_acc[1]; }

// ---------------- host launch ----------------
extern "C" void kernel_launch(void* const* d_in, const int* in_sizes, int n_in,
                              void* d_out, int out_size)
{
    const float* audio = 0;
    const int* labels = 0;
    const int* alen = 0;
    const int* llen = 0;
    for (int i = 0; i < 4; i++) {
        int sz = in_sizes[i];
        if (sz == Bc * TAc * LATENTc) { audio = (const float*)d_in[i]; }
        else if (sz == Bc * Lc) { labels = (const int*)d_in[i]; }
        else if (sz == Bc) {
            if (alen == 0) { alen = (const int*)d_in[i]; }
            else { llen = (const int*)d_in[i]; }
        }
    }
    const float* text_emb_w   = (const float*)d_in[4];
    const float* text_head_w  = (const float*)d_in[5];
    const float* audio_proj_w = (const float*)d_in[6];
    const float* audio_proj_b = (const float*)d_in[7];
    const float* start_emb    = (const float*)d_in[8];
    const float* aps          = (const float*)d_in[9];
    const float* tps          = (const float*)d_in[10];
    const float* ln1_g        = (const float*)d_in[11];
    const float* ln2_g        = (const float*)d_in[12];
    const float* lnf_g        = (const float*)d_in[13];
    const float* qkv_w        = (const float*)d_in[14];
    const float* attn_o_w     = (const float*)d_in[15];
    const float* fc_w         = (const float*)d_in[16];
    const float* mlp_o_w      = (const float*)d_in[17];

    void *vpx, *vphb, *vpqkv, *vpattnb, *vpfcb, *vpaudioH, *vneed;
    void *vwqkv, *vwattno, *vwfc, *vwmlpo, *vwaudio, *vaudiob;
    cudaGetSymbolAddress(&vpx,      g_x);
    cudaGetSymbolAddress(&vphb,     g_hb);
    cudaGetSymbolAddress(&vpqkv,    g_qkvb);
    cudaGetSymbolAddress(&vpattnb,  g_attnb);
    cudaGetSymbolAddress(&vpfcb,    g_fcb);
    cudaGetSymbolAddress(&vpaudioH, g_audioH);
    cudaGetSymbolAddress(&vneed,    g_need);
    cudaGetSymbolAddress(&vwqkv,    wb_qkv);
    cudaGetSymbolAddress(&vwattno,  wb_attno);
    cudaGetSymbolAddress(&vwfc,     wb_fc);
    cudaGetSymbolAddress(&vwmlpo,   wb_mlpo);
    cudaGetSymbolAddress(&vwaudio,  wb_audio);
    cudaGetSymbolAddress(&vaudiob,  g_audio_b);

    float* px      = (float*)vpx;
    bf16*  phb     = (bf16*)vphb;
    bf16*  pqkv    = (bf16*)vpqkv;
    bf16*  pattnb  = (bf16*)vpattnb;
    bf16*  pfcb    = (bf16*)vpfcb;
    float* paudioH = (float*)vpaudioH;
    int*   pneed   = (int*)vneed;
    bf16*  pwqkv   = (bf16*)vwqkv;
    bf16*  pwattno = (bf16*)vwattno;
    bf16*  pwfc    = (bf16*)vwfc;
    bf16*  pwmlpo  = (bf16*)vwmlpo;
    bf16*  pwaudio = (bf16*)vwaudio;
    bf16*  paudiob = (bf16*)vaudiob;

    // opt-in to 60KB dynamic smem for all GEMM instantiations
    cudaFuncSetAttribute(gemm_bf16<0,1>, cudaFuncAttributeMaxDynamicSharedMemorySize, GEMM_SMEM);
    cudaFuncSetAttribute(gemm_bf16<1,0>, cudaFuncAttributeMaxDynamicSharedMemorySize, GEMM_SMEM);
    cudaFuncSetAttribute(gemm_bf16<2,1>, cudaFuncAttributeMaxDynamicSharedMemorySize, GEMM_SMEM);
    cudaFuncSetAttribute(gemm_bf16<3,0>, cudaFuncAttributeMaxDynamicSharedMemorySize, GEMM_SMEM);

    init_kernel<<<1, 32>>>(alen, llen);

    // f32 -> bf16 conversions (weights + audio input)
    {
        int n;
        n = Bc * TAc * LATENTc; f2b_kernel<<<(n / 4 + 255) / 256, 256>>>(audio, paudiob, n);
        n = Dc * LATENTc;       f2b_kernel<<<(n / 4 + 255) / 256, 256>>>(audio_proj_w, pwaudio, n);
        n = NLc * 3 * Dc * Dc;  f2b_kernel<<<(n / 4 + 255) / 256, 256>>>(qkv_w, pwqkv, n);
        n = NLc * Dc * Dc;      f2b_kernel<<<(n / 4 + 255) / 256, 256>>>(attn_o_w, pwattno, n);
        n = NLc * 4 * Dc * Dc;  f2b_kernel<<<(n / 4 + 255) / 256, 256>>>(fc_w, pwfc, n);
        n = NLc * 4 * Dc * Dc;  f2b_kernel<<<(n / 4 + 255) / 256, 256>>>(mlp_o_w, pwmlpo, n);
    }

    // audio projection: rows beyond alen[b] are never read by embed -> cull via alen
    gemm_bf16<1, 0><<<dim3(Dc / 64, (MAUD + 127) / 128), 256, GEMM_SMEM>>>(
        paudiob, pwaudio, audio_proj_b, paudioH, MAUD, Dc, LATENTc, alen, TAc);

    embed_kernel<<<MROWS, 256>>>(px, paudioH, text_emb_w, labels, alen, llen,
                                 start_emb, aps, tps);

    for (int l = 0; l < NLc; l++) {
        ln_kernel<<<MROWS, 256>>>(px, ln1_g + l * Dc, phb, pneed);
        gemm_bf16<0, 1><<<dim3(3 * Dc / 64, MROWS / 128), 256, GEMM_SMEM>>>(
            phb, pwqkv + (size_t)l * 3 * Dc * Dc, 0, pqkv, MROWS, 3 * Dc, Dc, pneed, Sc);
        attn_kernel<<<dim3((Sc + 63) / 64, Bc * Hc), 128>>>(pqkv, pattnb, pneed);
        gemm_bf16<3, 0><<<dim3(Dc / 64, MROWS / 128), 256, GEMM_SMEM>>>(
            pattnb, pwattno + (size_t)l * Dc * Dc, px, px, MROWS, Dc, Dc, pneed, Sc);
        ln_kernel<<<MROWS, 256>>>(px, ln2_g + l * Dc, phb, pneed);
        gemm_bf16<2, 1><<<dim3(4 * Dc / 64, MROWS / 128), 256, GEMM_SMEM>>>(
            phb, pwfc + (size_t)l * 4 * Dc * Dc, 0, pfcb, MROWS, 4 * Dc, Dc, pneed, Sc);
        gemm_bf16<3, 0><<<dim3(Dc / 64, MROWS / 128), 256, GEMM_SMEM>>>(
            pfcb, pwmlpo + (size_t)l * 4 * Dc * Dc, px, px, MROWS, Dc, 4 * Dc, pneed, Sc);
    }

    ln_kernel<<<MROWS, 256>>>(px, lnf_g, phb, pneed);
    loss_kernel<<<Bc * Lc, 128>>>(phb, text_head_w, labels, alen, llen);
    finalize_kernel<<<1, 1>>>((float*)d_out);
}